// round 1
// baseline (speedup 1.0000x reference)
#include <cuda_runtime.h>
#include <cstddef>
#include <cstdint>

#define NB 128  // batch

// ---------------- output layout (tuple concat, fp32) ----------------
// (out, penul, L1b, L1r, L2b, L2r, L3b, L3r, L4b, L4r, L5b, L5r)
static const size_t O_OUT   = 0;          // 128*10        = 1280
static const size_t O_PENUL = 1280;       // 128*8192      = 1048576
static const size_t O_L1B   = 1049856;    // 128*128*16*16 = 4194304
static const size_t O_L1R   = 5244160;
static const size_t O_L2B   = 9438464;    // 128*256*16*16 = 8388608
static const size_t O_L2R   = 17827072;
static const size_t O_L3B   = 26215680;   // 128*256*8*8   = 2097152
static const size_t O_L3R   = 28312832;
static const size_t O_L4B   = 30409984;   // 128*512*8*8   = 4194304
static const size_t O_L4R   = 34604288;
static const size_t O_L5B   = 38798592;   // 128*512*4*4   = 1048576
static const size_t O_L5R   = 39847168;   // total 40895744

// ---------------- scratch (static device globals; no allocation) ----------------
__device__ float g_convB[16777216];   // binary-branch conv out (max 128*128*32*32)
__device__ float g_convR[16777216];   // real-branch conv out
__device__ float g_x[16777216];       // x after conv0+BN+hardtanh
__device__ float g_poolB[4194304];
__device__ float g_poolR[4194304];
__device__ float g_bw[4571136];       // signed standardized weights, 5 sets
__device__ float g_mean[1024];        // two sets of <=512
__device__ float g_rstd[1024];

// bw offsets
static const size_t BW1 = 0;         // 128*128*9 = 147456
static const size_t BW2 = 147456;    // 256*128*9 = 294912
static const size_t BW3 = 442368;    // 256*256*9 = 589824
static const size_t BW4 = 1032192;   // 512*256*9 = 1179648
static const size_t BW5 = 2211840;   // 512*512*9 = 2359296

// ---------------- weight sign kernel: bw = sign(w - mean_per_oc) ----------------
__global__ void wsign_k(const float* __restrict__ w, float* __restrict__ bw, int K) {
    int oc = blockIdx.x;
    int tid = threadIdx.x;
    const float* wp = w + (size_t)oc * K;
    double s = 0.0;
    for (int i = tid; i < K; i += 256) s += (double)wp[i];
    __shared__ double sh[256];
    sh[tid] = s; __syncthreads();
    for (int st = 128; st > 0; st >>= 1) {
        if (tid < st) sh[tid] += sh[tid + st];
        __syncthreads();
    }
    float m = (float)(sh[0] / (double)K);
    float* bp = bw + (size_t)oc * K;
    for (int i = tid; i < K; i += 256) {
        float d = wp[i] - m;
        bp[i] = (d > 0.f) ? 1.f : ((d < 0.f) ? -1.f : 0.f);
    }
}

// ---------------- direct 3x3 conv, pad 1, NCHW ----------------
// Block: 64 out-channels x 8x8 spatial tile. 256 thr, each 4oc x 4pos.
template<int CIN, int HH, bool SIGN_IN>
__global__ void __launch_bounds__(256) conv3x3_k(const float* __restrict__ in,
                                                 const float* __restrict__ w,
                                                 float* __restrict__ out) {
    const int TILES = HH / 8;
    int tile = blockIdx.x;
    int ty0 = (tile / TILES) * 8;
    int tx0 = (tile % TILES) * 8;
    int oc0 = blockIdx.y * 64;
    int n   = blockIdx.z;
    int Cout = gridDim.y * 64;
    int tid = threadIdx.x;
    int pos_t = tid & 15;   // 16 position groups, 4 positions each (stride 16)
    int oc_t  = tid >> 4;   // 16 oc groups, 4 consecutive oc each

    __shared__ float As[9][64];    // [tap][oc]
    __shared__ float Bs[10][10];   // input patch with halo

    float acc[4][4];
#pragma unroll
    for (int j = 0; j < 4; j++)
#pragma unroll
        for (int i = 0; i < 4; i++) acc[j][i] = 0.f;

    const float* inN = in + (size_t)n * CIN * HH * HH;

    for (int cin = 0; cin < CIN; cin++) {
        // stage weights: 64 oc x 9 taps
        for (int idx = tid; idx < 576; idx += 256) {
            int oc = idx / 9, tap = idx % 9;
            As[tap][oc] = w[(((size_t)(oc0 + oc)) * CIN + cin) * 9 + tap];
        }
        // stage 10x10 patch (zero-padded)
        if (tid < 100) {
            int r = tid / 10, c = tid % 10;
            int gy = ty0 + r - 1, gx = tx0 + c - 1;
            float v = 0.f;
            if (gy >= 0 && gy < HH && gx >= 0 && gx < HH)
                v = inN[(size_t)cin * HH * HH + gy * HH + gx];
            if (SIGN_IN) v = (v > 0.f) ? 1.f : ((v < 0.f) ? -1.f : 0.f);
            Bs[r][c] = v;
        }
        __syncthreads();
#pragma unroll
        for (int tap = 0; tap < 9; tap++) {
            int dy = tap / 3, dx = tap % 3;
            float4 wv = *(const float4*)&As[tap][oc_t * 4];
#pragma unroll
            for (int j = 0; j < 4; j++) {
                int p = pos_t + 16 * j;
                float bv = Bs[(p >> 3) + dy][(p & 7) + dx];
                acc[j][0] += bv * wv.x;
                acc[j][1] += bv * wv.y;
                acc[j][2] += bv * wv.z;
                acc[j][3] += bv * wv.w;
            }
        }
        __syncthreads();
    }

#pragma unroll
    for (int j = 0; j < 4; j++) {
        int p = pos_t + 16 * j;
        int oy = ty0 + (p >> 3), ox = tx0 + (p & 7);
#pragma unroll
        for (int i = 0; i < 4; i++) {
            int oc = oc0 + oc_t * 4 + i;
            out[(((size_t)n * Cout + oc) * HH + oy) * HH + ox] = acc[j][i];
        }
    }
}

// ---------------- BN stats (training-mode, biased var), double accumulation ----------------
__global__ void bnstats_k(const float* __restrict__ x, int C, int HW,
                          float* __restrict__ mean, float* __restrict__ rstd) {
    int c = blockIdx.x;
    int tid = threadIdx.x;
    double s1 = 0.0, s2 = 0.0;
    for (int n = 0; n < NB; n++) {
        const float* xp = x + ((size_t)n * C + c) * HW;
        for (int p = tid; p < HW; p += 256) {
            float v = xp[p];
            s1 += (double)v;
            s2 += (double)v * (double)v;
        }
    }
    __shared__ double sh1[256], sh2[256];
    sh1[tid] = s1; sh2[tid] = s2; __syncthreads();
    for (int st = 128; st > 0; st >>= 1) {
        if (tid < st) { sh1[tid] += sh1[tid + st]; sh2[tid] += sh2[tid + st]; }
        __syncthreads();
    }
    if (tid == 0) {
        double M = (double)NB * HW;
        double m = sh1[0] / M;
        double var = sh2[0] / M - m * m;
        mean[c] = (float)m;
        rstd[c] = (float)(1.0 / sqrt(var + 1e-5));
    }
}

// ---------------- BN apply + hardtanh ----------------
// C and HW are powers of two: pass lgHW and Cmask.
__global__ void bnht_k(const float* __restrict__ x, float* __restrict__ y,
                       const float* __restrict__ mean, const float* __restrict__ rstd,
                       const float* __restrict__ g, const float* __restrict__ bb,
                       int lgHW, int Cmask) {
    size_t i = (size_t)blockIdx.x * 256 + threadIdx.x;
    int c = (int)((i >> lgHW) & (size_t)Cmask);
    float v = (x[i] - mean[c]) * rstd[c] * g[c] + bb[c];
    y[i] = fminf(1.f, fmaxf(-1.f, v));
}

// ---------------- 2x2 maxpool stride 2 ----------------
__global__ void pool_k(const float* __restrict__ x, float* __restrict__ y,
                       int C, int Hout) {
    int i = blockIdx.x * 256 + threadIdx.x;
    int ox = i % Hout; int t = i / Hout;
    int oy = t % Hout; t /= Hout;
    int c = t % C; int n = t / C;
    int Hin = Hout * 2;
    const float* p = x + (((size_t)n * C + c) * Hin + oy * 2) * Hin + ox * 2;
    y[i] = fmaxf(fmaxf(p[0], p[1]), fmaxf(p[Hin], p[Hin + 1]));
}

// ---------------- copy ----------------
__global__ void copy_k(const float* __restrict__ src, float* __restrict__ dst) {
    size_t i = (size_t)blockIdx.x * 256 + threadIdx.x;
    dst[i] = src[i];
}

// ---------------- FC: out[n][j] = penul[n] . fc_w[j] + fc_b[j] ----------------
__global__ void fc_k(const float* __restrict__ p, const float* __restrict__ w,
                     const float* __restrict__ b, float* __restrict__ out) {
    int n = blockIdx.x;
    int tid = threadIdx.x;
    float acc[10];
#pragma unroll
    for (int j = 0; j < 10; j++) acc[j] = 0.f;
    const float* pn = p + (size_t)n * 8192;
    for (int k = tid; k < 8192; k += 256) {
        float pv = pn[k];
#pragma unroll
        for (int j = 0; j < 10; j++) acc[j] += pv * w[(size_t)j * 8192 + k];
    }
    __shared__ float sh[256];
    for (int j = 0; j < 10; j++) {
        sh[tid] = acc[j]; __syncthreads();
        for (int st = 128; st > 0; st >>= 1) {
            if (tid < st) sh[tid] += sh[tid + st];
            __syncthreads();
        }
        if (tid == 0) out[n * 10 + j] = sh[0] + b[j];
        __syncthreads();
    }
}

// ---------------- host launch ----------------
extern "C" void kernel_launch(void* const* d_in, const int* in_sizes, int n_in,
                              void* d_out, int out_size) {
    (void)in_sizes; (void)n_in; (void)out_size;
    const float* x   = (const float*)d_in[0];
    const float* w0  = (const float*)d_in[1];
    const float* w1  = (const float*)d_in[2];
    const float* w2  = (const float*)d_in[3];
    const float* w3  = (const float*)d_in[4];
    const float* w4  = (const float*)d_in[5];
    const float* w5  = (const float*)d_in[6];
    const float* fcw = (const float*)d_in[7];
    const float* fcb = (const float*)d_in[8];
    const float* G[6], *B[6];
    for (int i = 0; i < 6; i++) { G[i] = (const float*)d_in[9 + 2*i]; B[i] = (const float*)d_in[10 + 2*i]; }
    float* out = (float*)d_out;

    float *convB, *convR, *xb, *poolB, *poolR, *bw, *mean, *rstd;
    cudaGetSymbolAddress((void**)&convB, g_convB);
    cudaGetSymbolAddress((void**)&convR, g_convR);
    cudaGetSymbolAddress((void**)&xb,    g_x);
    cudaGetSymbolAddress((void**)&poolB, g_poolB);
    cudaGetSymbolAddress((void**)&poolR, g_poolR);
    cudaGetSymbolAddress((void**)&bw,    g_bw);
    cudaGetSymbolAddress((void**)&mean,  g_mean);
    cudaGetSymbolAddress((void**)&rstd,  g_rstd);

    // ---- binary weights: sign(w - per-oc mean) ----
    wsign_k<<<128, 256>>>(w1, bw + BW1, 128 * 9);
    wsign_k<<<256, 256>>>(w2, bw + BW2, 128 * 9);
    wsign_k<<<256, 256>>>(w3, bw + BW3, 256 * 9);
    wsign_k<<<512, 256>>>(w4, bw + BW4, 256 * 9);
    wsign_k<<<512, 256>>>(w5, bw + BW5, 512 * 9);

    // ---- stage 0: conv0 + BN0 + hardtanh -> g_x ----
    conv3x3_k<3, 32, false><<<dim3(16, 2, NB), 256>>>(x, w0, convB);
    bnstats_k<<<128, 256>>>(convB, 128, 1024, mean, rstd);
    bnht_k<<<(NB * 128 * 1024) / 256, 256>>>(convB, xb, mean, rstd, G[0], B[0], 10, 127);

    // ---- Layer 1: 128->128 @32, pool -> 16 ----
    conv3x3_k<128, 32, true ><<<dim3(16, 2, NB), 256>>>(xb, bw + BW1, convB);
    conv3x3_k<128, 32, false><<<dim3(16, 2, NB), 256>>>(xb, w1,       convR);
    pool_k<<<(NB * 128 * 256) / 256, 256>>>(convB, poolB, 128, 16);
    pool_k<<<(NB * 128 * 256) / 256, 256>>>(convR, poolR, 128, 16);
    bnstats_k<<<128, 256>>>(poolB, 128, 256, mean, rstd);
    bnht_k<<<(NB * 128 * 256) / 256, 256>>>(poolB, out + O_L1B, mean, rstd, G[1], B[1], 8, 127);
    bnstats_k<<<128, 256>>>(poolR, 128, 256, mean + 512, rstd + 512);
    bnht_k<<<(NB * 128 * 256) / 256, 256>>>(poolR, out + O_L1R, mean + 512, rstd + 512, G[1], B[1], 8, 127);

    // ---- Layer 2: 128->256 @16, no pool ----
    conv3x3_k<128, 16, true ><<<dim3(4, 4, NB), 256>>>(out + O_L1B, bw + BW2, convB);
    conv3x3_k<128, 16, false><<<dim3(4, 4, NB), 256>>>(out + O_L1R, w2,       convR);
    bnstats_k<<<256, 256>>>(convB, 256, 256, mean, rstd);
    bnht_k<<<(NB * 256 * 256) / 256, 256>>>(convB, out + O_L2B, mean, rstd, G[2], B[2], 8, 255);
    bnstats_k<<<256, 256>>>(convR, 256, 256, mean + 512, rstd + 512);
    bnht_k<<<(NB * 256 * 256) / 256, 256>>>(convR, out + O_L2R, mean + 512, rstd + 512, G[2], B[2], 8, 255);

    // ---- Layer 3: 256->256 @16, pool -> 8 ----
    conv3x3_k<256, 16, true ><<<dim3(4, 4, NB), 256>>>(out + O_L2B, bw + BW3, convB);
    conv3x3_k<256, 16, false><<<dim3(4, 4, NB), 256>>>(out + O_L2R, w3,       convR);
    pool_k<<<(NB * 256 * 64) / 256, 256>>>(convB, poolB, 256, 8);
    pool_k<<<(NB * 256 * 64) / 256, 256>>>(convR, poolR, 256, 8);
    bnstats_k<<<256, 256>>>(poolB, 256, 64, mean, rstd);
    bnht_k<<<(NB * 256 * 64) / 256, 256>>>(poolB, out + O_L3B, mean, rstd, G[3], B[3], 6, 255);
    bnstats_k<<<256, 256>>>(poolR, 256, 64, mean + 512, rstd + 512);
    bnht_k<<<(NB * 256 * 64) / 256, 256>>>(poolR, out + O_L3R, mean + 512, rstd + 512, G[3], B[3], 6, 255);

    // ---- Layer 4: 256->512 @8, no pool ----
    conv3x3_k<256, 8, true ><<<dim3(1, 8, NB), 256>>>(out + O_L3B, bw + BW4, convB);
    conv3x3_k<256, 8, false><<<dim3(1, 8, NB), 256>>>(out + O_L3R, w4,       convR);
    bnstats_k<<<512, 256>>>(convB, 512, 64, mean, rstd);
    bnht_k<<<(NB * 512 * 64) / 256, 256>>>(convB, out + O_L4B, mean, rstd, G[4], B[4], 6, 511);
    bnstats_k<<<512, 256>>>(convR, 512, 64, mean + 512, rstd + 512);
    bnht_k<<<(NB * 512 * 64) / 256, 256>>>(convR, out + O_L4R, mean + 512, rstd + 512, G[4], B[4], 6, 511);

    // ---- Layer 5: 512->512 @8, pool -> 4 ----
    conv3x3_k<512, 8, true ><<<dim3(1, 8, NB), 256>>>(out + O_L4B, bw + BW5, convB);
    conv3x3_k<512, 8, false><<<dim3(1, 8, NB), 256>>>(out + O_L4R, w5,       convR);
    pool_k<<<(NB * 512 * 16) / 256, 256>>>(convB, poolB, 512, 4);
    pool_k<<<(NB * 512 * 16) / 256, 256>>>(convR, poolR, 512, 4);
    bnstats_k<<<512, 256>>>(poolB, 512, 16, mean, rstd);
    bnht_k<<<(NB * 512 * 16) / 256, 256>>>(poolB, out + O_L5B, mean, rstd, G[5], B[5], 4, 511);
    bnstats_k<<<512, 256>>>(poolR, 512, 16, mean + 512, rstd + 512);
    bnht_k<<<(NB * 512 * 16) / 256, 256>>>(poolR, out + O_L5R, mean + 512, rstd + 512, G[5], B[5], 4, 511);

    // ---- penul copy + FC ----
    copy_k<<<(NB * 8192) / 256, 256>>>(out + O_L5B, out + O_PENUL);
    fc_k<<<NB, 256>>>(out + O_PENUL, fcw, fcb, out + O_OUT);
}

// round 3
// speedup vs baseline: 2.1025x; 2.1025x over previous
#include <cuda_runtime.h>
#include <cstddef>
#include <cstdint>

#define NB 128  // batch

// ---------------- output layout (tuple concat, fp32) ----------------
static const size_t O_OUT   = 0;
static const size_t O_PENUL = 1280;
static const size_t O_L1B   = 1049856;
static const size_t O_L1R   = 5244160;
static const size_t O_L2B   = 9438464;
static const size_t O_L2R   = 17827072;
static const size_t O_L3B   = 26215680;
static const size_t O_L3R   = 28312832;
static const size_t O_L4B   = 30409984;
static const size_t O_L4R   = 34604288;
static const size_t O_L5B   = 38798592;
static const size_t O_L5R   = 39847168;

// ---------------- scratch ----------------
__device__ float g_convB[16777216];
__device__ float g_convR[16777216];
__device__ float g_x[16777216];
__device__ float g_poolB[4194304];
__device__ float g_poolR[4194304];
__device__ float g_bw[4571136];
__device__ float g_mean[1024];
__device__ float g_rstd[1024];

static const size_t BW1 = 0;
static const size_t BW2 = 147456;
static const size_t BW3 = 442368;
static const size_t BW4 = 1032192;
static const size_t BW5 = 2211840;

// ---------------- weight sign kernel ----------------
__global__ void wsign_k(const float* __restrict__ w, float* __restrict__ bw, int K) {
    int oc = blockIdx.x;
    int tid = threadIdx.x;
    const float* wp = w + (size_t)oc * K;
    double s = 0.0;
    for (int i = tid; i < K; i += 256) s += (double)wp[i];
    __shared__ double sh[256];
    sh[tid] = s; __syncthreads();
    for (int st = 128; st > 0; st >>= 1) {
        if (tid < st) sh[tid] += sh[tid + st];
        __syncthreads();
    }
    float m = (float)(sh[0] / (double)K);
    float* bp = bw + (size_t)oc * K;
    for (int i = tid; i < K; i += 256) {
        float d = wp[i] - m;
        bp[i] = (d > 0.f) ? 1.f : ((d < 0.f) ? -1.f : 0.f);
    }
}

// ---------------- FFMA direct conv (conv0 only, Cin=3) ----------------
template<int CIN, int HH, bool SIGN_IN>
__global__ void __launch_bounds__(256) conv3x3_k(const float* __restrict__ in,
                                                 const float* __restrict__ w,
                                                 float* __restrict__ out) {
    const int TILES = HH / 8;
    int tile = blockIdx.x;
    int ty0 = (tile / TILES) * 8;
    int tx0 = (tile % TILES) * 8;
    int oc0 = blockIdx.y * 64;
    int n   = blockIdx.z;
    int Cout = gridDim.y * 64;
    int tid = threadIdx.x;
    int pos_t = tid & 15;
    int oc_t  = tid >> 4;

    __shared__ float As[9][64];
    __shared__ float Bs[10][10];

    float acc[4][4];
#pragma unroll
    for (int j = 0; j < 4; j++)
#pragma unroll
        for (int i = 0; i < 4; i++) acc[j][i] = 0.f;

    const float* inN = in + (size_t)n * CIN * HH * HH;

    for (int cin = 0; cin < CIN; cin++) {
        for (int idx = tid; idx < 576; idx += 256) {
            int oc = idx / 9, tap = idx % 9;
            As[tap][oc] = w[(((size_t)(oc0 + oc)) * CIN + cin) * 9 + tap];
        }
        if (tid < 100) {
            int r = tid / 10, c = tid % 10;
            int gy = ty0 + r - 1, gx = tx0 + c - 1;
            float v = 0.f;
            if (gy >= 0 && gy < HH && gx >= 0 && gx < HH)
                v = inN[(size_t)cin * HH * HH + gy * HH + gx];
            if (SIGN_IN) v = (v > 0.f) ? 1.f : ((v < 0.f) ? -1.f : 0.f);
            Bs[r][c] = v;
        }
        __syncthreads();
#pragma unroll
        for (int tap = 0; tap < 9; tap++) {
            int dy = tap / 3, dx = tap % 3;
            float4 wv = *(const float4*)&As[tap][oc_t * 4];
#pragma unroll
            for (int j = 0; j < 4; j++) {
                int p = pos_t + 16 * j;
                float bv = Bs[(p >> 3) + dy][(p & 7) + dx];
                acc[j][0] += bv * wv.x;
                acc[j][1] += bv * wv.y;
                acc[j][2] += bv * wv.z;
                acc[j][3] += bv * wv.w;
            }
        }
        __syncthreads();
    }

#pragma unroll
    for (int j = 0; j < 4; j++) {
        int p = pos_t + 16 * j;
        int oy = ty0 + (p >> 3), ox = tx0 + (p & 7);
#pragma unroll
        for (int i = 0; i < 4; i++) {
            int oc = oc0 + oc_t * 4 + i;
            out[(((size_t)n * Cout + oc) * HH + oy) * HH + ox] = acc[j][i];
        }
    }
}

// ---------------- tf32 warp MMA helpers ----------------
__device__ __forceinline__ uint32_t f2tf32(float x) {
    uint32_t r;
    asm("cvt.rna.tf32.f32 %0, %1;" : "=r"(r) : "f"(x));
    return r;
}

__device__ __forceinline__ void mma_tf32(float* d, const uint32_t* a, const uint32_t* b) {
    asm volatile(
        "mma.sync.aligned.m16n8k8.row.col.f32.tf32.tf32.f32 "
        "{%0,%1,%2,%3}, {%4,%5,%6,%7}, {%8,%9}, {%0,%1,%2,%3};\n"
        : "+f"(d[0]), "+f"(d[1]), "+f"(d[2]), "+f"(d[3])
        : "r"(a[0]), "r"(a[1]), "r"(a[2]), "r"(a[3]),
          "r"(b[0]), "r"(b[1]));
}

// ---------------- implicit-GEMM conv via tf32 MMA ----------------
// Block: M=128 (oc) x N=64 (positions). 128 threads, 4 warps; warp tile 32x64.
// K = CIN*9, chunked by 16.
// SPLIT=true: 3xTF32 decomposition (hi/lo) for near-fp32 precision (real branch).
template<int CIN, int H, bool SIGN_IN, bool SPLIT>
__global__ void __launch_bounds__(128) convmma_k(const float* __restrict__ in,
                                                 const float* __restrict__ w,
                                                 float* __restrict__ out,
                                                 int Cout) {
    constexpr int Wd = H;
    constexpr int HW = H * H;
    constexpr int K  = CIN * 9;
    constexpr int LGHW = (HW == 1024) ? 10 : (HW == 256) ? 8 : 6;
    constexpr int LGW  = (H == 32) ? 5 : (H == 16) ? 4 : 3;
    constexpr int NS = SPLIT ? 2 : 1;

    __shared__ uint32_t As[NS][16][136];  // [hi/lo][k][m], stride 136
    __shared__ uint32_t Bs[NS][16][72];   // [hi/lo][k][n], stride 72

    int tid  = threadIdx.x;
    int lane = tid & 31;
    int warp = tid >> 5;
    int gid  = lane >> 2;   // 0..7
    int tig  = lane & 3;    // 0..3

    int col0 = blockIdx.x * 64;
    int oc0  = blockIdx.y * 128;

    int bc  = tid & 63;
    int br2 = tid >> 6;
    int gcol = col0 + bc;
    int n   = gcol >> LGHW;
    int pos = gcol & (HW - 1);
    int y   = pos >> LGW;
    int x   = pos & (Wd - 1);
    const float* inN = in + (size_t)n * CIN * HW;

    int cin8[8], tap8[8];
#pragma unroll
    for (int i = 0; i < 8; i++) {
        int r = br2 + 2 * i;
        cin8[i] = r / 9;
        tap8[i] = r % 9;
    }

    float acc[2][8][4];
#pragma unroll
    for (int mt = 0; mt < 2; mt++)
#pragma unroll
        for (int nt = 0; nt < 8; nt++)
#pragma unroll
            for (int r = 0; r < 4; r++) acc[mt][nt][r] = 0.f;

    const float* wA = w + (size_t)(oc0 + tid) * K;

    for (int k0 = 0; k0 < K; k0 += 16) {
        // stage A (weights)
#pragma unroll
        for (int j = 0; j < 4; j++) {
            float4 v = *(const float4*)(wA + k0 + 4 * j);
            float vs[4] = {v.x, v.y, v.z, v.w};
#pragma unroll
            for (int e = 0; e < 4; e++) {
                uint32_t hi = f2tf32(vs[e]);
                As[0][4 * j + e][tid] = hi;
                if (SPLIT) {
                    float lo = vs[e] - __uint_as_float(hi);
                    As[1][4 * j + e][tid] = f2tf32(lo);
                }
            }
        }
        // stage B (im2col gather)
#pragma unroll
        for (int i = 0; i < 8; i++) {
            int tap = tap8[i];
            int yy = y + tap / 3 - 1;
            int xx = x + tap % 3 - 1;
            float v = 0.f;
            if (yy >= 0 && yy < H && xx >= 0 && xx < Wd)
                v = inN[cin8[i] * HW + yy * Wd + xx];
            if (SIGN_IN) v = (v > 0.f) ? 1.f : ((v < 0.f) ? -1.f : 0.f);
            uint32_t hi = f2tf32(v);
            Bs[0][br2 + 2 * i][bc] = hi;
            if (SPLIT) {
                float lo = v - __uint_as_float(hi);
                Bs[1][br2 + 2 * i][bc] = f2tf32(lo);
            }
            tap8[i] += 7;
            cin8[i] += 1;
            if (tap8[i] >= 9) { tap8[i] -= 9; cin8[i] += 1; }
        }
        __syncthreads();

#pragma unroll
        for (int ks = 0; ks < 2; ks++) {
            uint32_t af[NS][2][4], bf[NS][8][2];
#pragma unroll
            for (int s = 0; s < NS; s++) {
#pragma unroll
                for (int mt = 0; mt < 2; mt++) {
                    int m = warp * 32 + mt * 16 + gid;
                    af[s][mt][0] = As[s][ks * 8 + tig][m];
                    af[s][mt][1] = As[s][ks * 8 + tig][m + 8];
                    af[s][mt][2] = As[s][ks * 8 + tig + 4][m];
                    af[s][mt][3] = As[s][ks * 8 + tig + 4][m + 8];
                }
#pragma unroll
                for (int nt = 0; nt < 8; nt++) {
                    bf[s][nt][0] = Bs[s][ks * 8 + tig][nt * 8 + gid];
                    bf[s][nt][1] = Bs[s][ks * 8 + tig + 4][nt * 8 + gid];
                }
            }
#pragma unroll
            for (int mt = 0; mt < 2; mt++)
#pragma unroll
                for (int nt = 0; nt < 8; nt++) {
                    if (SPLIT) {
                        // lo terms first, hi*hi last (largest magnitude added last)
                        mma_tf32(acc[mt][nt], af[1][mt], bf[0][nt]);
                        mma_tf32(acc[mt][nt], af[0][mt], bf[1][nt]);
                    }
                    mma_tf32(acc[mt][nt], af[0][mt], bf[0][nt]);
                }
        }
        __syncthreads();
    }

    // epilogue: adjacent column pairs -> float2 stores
#pragma unroll
    for (int mt = 0; mt < 2; mt++) {
#pragma unroll
        for (int nt = 0; nt < 8; nt++) {
            int c = col0 + nt * 8 + 2 * tig;
            int n_  = c >> LGHW;
            int pp  = c & (HW - 1);
#pragma unroll
            for (int h = 0; h < 2; h++) {
                int m = oc0 + warp * 32 + mt * 16 + gid + 8 * h;
                float2 v = make_float2(acc[mt][nt][2 * h], acc[mt][nt][2 * h + 1]);
                *(float2*)&out[((size_t)n_ * Cout + m) * HW + pp] = v;
            }
        }
    }
}

// ---------------- BN stats ----------------
__global__ void bnstats_k(const float* __restrict__ x, int C, int HW,
                          float* __restrict__ mean, float* __restrict__ rstd) {
    int c = blockIdx.x;
    int tid = threadIdx.x;
    double s1 = 0.0, s2 = 0.0;
    for (int n = 0; n < NB; n++) {
        const float* xp = x + ((size_t)n * C + c) * HW;
        for (int p = tid; p < HW; p += 256) {
            float v = xp[p];
            s1 += (double)v;
            s2 += (double)v * (double)v;
        }
    }
    __shared__ double sh1[256], sh2[256];
    sh1[tid] = s1; sh2[tid] = s2; __syncthreads();
    for (int st = 128; st > 0; st >>= 1) {
        if (tid < st) { sh1[tid] += sh1[tid + st]; sh2[tid] += sh2[tid + st]; }
        __syncthreads();
    }
    if (tid == 0) {
        double M = (double)NB * HW;
        double m = sh1[0] / M;
        double var = sh2[0] / M - m * m;
        mean[c] = (float)m;
        rstd[c] = (float)(1.0 / sqrt(var + 1e-5));
    }
}

// ---------------- BN apply + hardtanh ----------------
__global__ void bnht_k(const float* __restrict__ x, float* __restrict__ y,
                       const float* __restrict__ mean, const float* __restrict__ rstd,
                       const float* __restrict__ g, const float* __restrict__ bb,
                       int lgHW, int Cmask) {
    size_t i = (size_t)blockIdx.x * 256 + threadIdx.x;
    int c = (int)((i >> lgHW) & (size_t)Cmask);
    float v = (x[i] - mean[c]) * rstd[c] * g[c] + bb[c];
    y[i] = fminf(1.f, fmaxf(-1.f, v));
}

// ---------------- 2x2 maxpool ----------------
__global__ void pool_k(const float* __restrict__ x, float* __restrict__ y,
                       int C, int Hout) {
    int i = blockIdx.x * 256 + threadIdx.x;
    int ox = i % Hout; int t = i / Hout;
    int oy = t % Hout; t /= Hout;
    int c = t % C; int n = t / C;
    int Hin = Hout * 2;
    const float* p = x + (((size_t)n * C + c) * Hin + oy * 2) * Hin + ox * 2;
    y[i] = fmaxf(fmaxf(p[0], p[1]), fmaxf(p[Hin], p[Hin + 1]));
}

// ---------------- copy ----------------
__global__ void copy_k(const float* __restrict__ src, float* __restrict__ dst) {
    size_t i = (size_t)blockIdx.x * 256 + threadIdx.x;
    dst[i] = src[i];
}

// ---------------- FC ----------------
__global__ void fc_k(const float* __restrict__ p, const float* __restrict__ w,
                     const float* __restrict__ b, float* __restrict__ out) {
    int n = blockIdx.x;
    int tid = threadIdx.x;
    float acc[10];
#pragma unroll
    for (int j = 0; j < 10; j++) acc[j] = 0.f;
    const float* pn = p + (size_t)n * 8192;
    for (int k = tid; k < 8192; k += 256) {
        float pv = pn[k];
#pragma unroll
        for (int j = 0; j < 10; j++) acc[j] += pv * w[(size_t)j * 8192 + k];
    }
    __shared__ float sh[256];
    for (int j = 0; j < 10; j++) {
        sh[tid] = acc[j]; __syncthreads();
        for (int st = 128; st > 0; st >>= 1) {
            if (tid < st) sh[tid] += sh[tid + st];
            __syncthreads();
        }
        if (tid == 0) out[n * 10 + j] = sh[0] + b[j];
        __syncthreads();
    }
}

// ---------------- host launch ----------------
extern "C" void kernel_launch(void* const* d_in, const int* in_sizes, int n_in,
                              void* d_out, int out_size) {
    (void)in_sizes; (void)n_in; (void)out_size;
    const float* x   = (const float*)d_in[0];
    const float* w0  = (const float*)d_in[1];
    const float* w1  = (const float*)d_in[2];
    const float* w2  = (const float*)d_in[3];
    const float* w3  = (const float*)d_in[4];
    const float* w4  = (const float*)d_in[5];
    const float* w5  = (const float*)d_in[6];
    const float* fcw = (const float*)d_in[7];
    const float* fcb = (const float*)d_in[8];
    const float* G[6], *B[6];
    for (int i = 0; i < 6; i++) { G[i] = (const float*)d_in[9 + 2*i]; B[i] = (const float*)d_in[10 + 2*i]; }
    float* out = (float*)d_out;

    float *convB, *convR, *xb, *poolB, *poolR, *bw, *mean, *rstd;
    cudaGetSymbolAddress((void**)&convB, g_convB);
    cudaGetSymbolAddress((void**)&convR, g_convR);
    cudaGetSymbolAddress((void**)&xb,    g_x);
    cudaGetSymbolAddress((void**)&poolB, g_poolB);
    cudaGetSymbolAddress((void**)&poolR, g_poolR);
    cudaGetSymbolAddress((void**)&bw,    g_bw);
    cudaGetSymbolAddress((void**)&mean,  g_mean);
    cudaGetSymbolAddress((void**)&rstd,  g_rstd);

    // binary weights
    wsign_k<<<128, 256>>>(w1, bw + BW1, 128 * 9);
    wsign_k<<<256, 256>>>(w2, bw + BW2, 128 * 9);
    wsign_k<<<256, 256>>>(w3, bw + BW3, 256 * 9);
    wsign_k<<<512, 256>>>(w4, bw + BW4, 256 * 9);
    wsign_k<<<512, 256>>>(w5, bw + BW5, 512 * 9);

    // stage 0: conv0 + BN0 + hardtanh
    conv3x3_k<3, 32, false><<<dim3(16, 2, NB), 256>>>(x, w0, convB);
    bnstats_k<<<128, 256>>>(convB, 128, 1024, mean, rstd);
    bnht_k<<<(NB * 128 * 1024) / 256, 256>>>(convB, xb, mean, rstd, G[0], B[0], 10, 127);

    // Layer 1: 128->128 @32, pool -> 16
    convmma_k<128, 32, true,  false><<<dim3(2048, 1), 128>>>(xb, bw + BW1, convB, 128);
    convmma_k<128, 32, false, true ><<<dim3(2048, 1), 128>>>(xb, w1,       convR, 128);
    pool_k<<<(NB * 128 * 256) / 256, 256>>>(convB, poolB, 128, 16);
    pool_k<<<(NB * 128 * 256) / 256, 256>>>(convR, poolR, 128, 16);
    bnstats_k<<<128, 256>>>(poolB, 128, 256, mean, rstd);
    bnht_k<<<(NB * 128 * 256) / 256, 256>>>(poolB, out + O_L1B, mean, rstd, G[1], B[1], 8, 127);
    bnstats_k<<<128, 256>>>(poolR, 128, 256, mean + 512, rstd + 512);
    bnht_k<<<(NB * 128 * 256) / 256, 256>>>(poolR, out + O_L1R, mean + 512, rstd + 512, G[1], B[1], 8, 127);

    // Layer 2: 128->256 @16
    convmma_k<128, 16, true,  false><<<dim3(512, 2), 128>>>(out + O_L1B, bw + BW2, convB, 256);
    convmma_k<128, 16, false, true ><<<dim3(512, 2), 128>>>(out + O_L1R, w2,       convR, 256);
    bnstats_k<<<256, 256>>>(convB, 256, 256, mean, rstd);
    bnht_k<<<(NB * 256 * 256) / 256, 256>>>(convB, out + O_L2B, mean, rstd, G[2], B[2], 8, 255);
    bnstats_k<<<256, 256>>>(convR, 256, 256, mean + 512, rstd + 512);
    bnht_k<<<(NB * 256 * 256) / 256, 256>>>(convR, out + O_L2R, mean + 512, rstd + 512, G[2], B[2], 8, 255);

    // Layer 3: 256->256 @16, pool -> 8
    convmma_k<256, 16, true,  false><<<dim3(512, 2), 128>>>(out + O_L2B, bw + BW3, convB, 256);
    convmma_k<256, 16, false, true ><<<dim3(512, 2), 128>>>(out + O_L2R, w3,       convR, 256);
    pool_k<<<(NB * 256 * 64) / 256, 256>>>(convB, poolB, 256, 8);
    pool_k<<<(NB * 256 * 64) / 256, 256>>>(convR, poolR, 256, 8);
    bnstats_k<<<256, 256>>>(poolB, 256, 64, mean, rstd);
    bnht_k<<<(NB * 256 * 64) / 256, 256>>>(poolB, out + O_L3B, mean, rstd, G[3], B[3], 6, 255);
    bnstats_k<<<256, 256>>>(poolR, 256, 64, mean + 512, rstd + 512);
    bnht_k<<<(NB * 256 * 64) / 256, 256>>>(poolR, out + O_L3R, mean + 512, rstd + 512, G[3], B[3], 6, 255);

    // Layer 4: 256->512 @8
    convmma_k<256, 8, true,  false><<<dim3(128, 4), 128>>>(out + O_L3B, bw + BW4, convB, 512);
    convmma_k<256, 8, false, true ><<<dim3(128, 4), 128>>>(out + O_L3R, w4,       convR, 512);
    bnstats_k<<<512, 256>>>(convB, 512, 64, mean, rstd);
    bnht_k<<<(NB * 512 * 64) / 256, 256>>>(convB, out + O_L4B, mean, rstd, G[4], B[4], 6, 511);
    bnstats_k<<<512, 256>>>(convR, 512, 64, mean + 512, rstd + 512);
    bnht_k<<<(NB * 512 * 64) / 256, 256>>>(convR, out + O_L4R, mean + 512, rstd + 512, G[4], B[4], 6, 511);

    // Layer 5: 512->512 @8, pool -> 4
    convmma_k<512, 8, true,  false><<<dim3(128, 4), 128>>>(out + O_L4B, bw + BW5, convB, 512);
    convmma_k<512, 8, false, true ><<<dim3(128, 4), 128>>>(out + O_L4R, w5,       convR, 512);
    pool_k<<<(NB * 512 * 16) / 256, 256>>>(convB, poolB, 512, 4);
    pool_k<<<(NB * 512 * 16) / 256, 256>>>(convR, poolR, 512, 4);
    bnstats_k<<<512, 256>>>(poolB, 512, 16, mean, rstd);
    bnht_k<<<(NB * 512 * 16) / 256, 256>>>(poolB, out + O_L5B, mean, rstd, G[5], B[5], 4, 511);
    bnstats_k<<<512, 256>>>(poolR, 512, 16, mean + 512, rstd + 512);
    bnht_k<<<(NB * 512 * 16) / 256, 256>>>(poolR, out + O_L5R, mean + 512, rstd + 512, G[5], B[5], 4, 511);

    // penul + FC
    copy_k<<<(NB * 8192) / 256, 256>>>(out + O_L5B, out + O_PENUL);
    fc_k<<<NB, 256>>>(out + O_PENUL, fcw, fcb, out + O_OUT);
}

// round 4
// speedup vs baseline: 2.6703x; 1.2700x over previous
#include <cuda_runtime.h>
#include <cstddef>
#include <cstdint>

#define NB 128  // batch

// ---------------- output layout (tuple concat, fp32) ----------------
static const size_t O_OUT   = 0;
static const size_t O_PENUL = 1280;
static const size_t O_L1B   = 1049856;
static const size_t O_L1R   = 5244160;
static const size_t O_L2B   = 9438464;
static const size_t O_L2R   = 17827072;
static const size_t O_L3B   = 26215680;
static const size_t O_L3R   = 28312832;
static const size_t O_L4B   = 30409984;
static const size_t O_L4R   = 34604288;
static const size_t O_L5B   = 38798592;
static const size_t O_L5R   = 39847168;

// ---------------- scratch ----------------
__device__ float g_convB[16777216];
__device__ float g_convR[16777216];
__device__ float g_x[16777216];
__device__ float g_poolB[4194304];
__device__ float g_poolR[4194304];
__device__ float g_bw[4571136];
__device__ float g_mean[1024];
__device__ float g_rstd[1024];

static const size_t BW1 = 0;
static const size_t BW2 = 147456;
static const size_t BW3 = 442368;
static const size_t BW4 = 1032192;
static const size_t BW5 = 2211840;

// ---------------- weight sign kernel ----------------
__global__ void wsign_k(const float* __restrict__ w, float* __restrict__ bw, int K) {
    int oc = blockIdx.x;
    int tid = threadIdx.x;
    const float* wp = w + (size_t)oc * K;
    double s = 0.0;
    for (int i = tid; i < K; i += 256) s += (double)wp[i];
    __shared__ double sh[256];
    sh[tid] = s; __syncthreads();
    for (int st = 128; st > 0; st >>= 1) {
        if (tid < st) sh[tid] += sh[tid + st];
        __syncthreads();
    }
    float m = (float)(sh[0] / (double)K);
    float* bp = bw + (size_t)oc * K;
    for (int i = tid; i < K; i += 256) {
        float d = wp[i] - m;
        bp[i] = (d > 0.f) ? 1.f : ((d < 0.f) ? -1.f : 0.f);
    }
}

// ---------------- FFMA direct conv (conv0 only, Cin=3) ----------------
template<int CIN, int HH, bool SIGN_IN>
__global__ void __launch_bounds__(256) conv3x3_k(const float* __restrict__ in,
                                                 const float* __restrict__ w,
                                                 float* __restrict__ out) {
    const int TILES = HH / 8;
    int tile = blockIdx.x;
    int ty0 = (tile / TILES) * 8;
    int tx0 = (tile % TILES) * 8;
    int oc0 = blockIdx.y * 64;
    int n   = blockIdx.z;
    int Cout = gridDim.y * 64;
    int tid = threadIdx.x;
    int pos_t = tid & 15;
    int oc_t  = tid >> 4;

    __shared__ float As[9][64];
    __shared__ float Bs[10][10];

    float acc[4][4];
#pragma unroll
    for (int j = 0; j < 4; j++)
#pragma unroll
        for (int i = 0; i < 4; i++) acc[j][i] = 0.f;

    const float* inN = in + (size_t)n * CIN * HH * HH;

    for (int cin = 0; cin < CIN; cin++) {
        for (int idx = tid; idx < 576; idx += 256) {
            int oc = idx / 9, tap = idx % 9;
            As[tap][oc] = w[(((size_t)(oc0 + oc)) * CIN + cin) * 9 + tap];
        }
        if (tid < 100) {
            int r = tid / 10, c = tid % 10;
            int gy = ty0 + r - 1, gx = tx0 + c - 1;
            float v = 0.f;
            if (gy >= 0 && gy < HH && gx >= 0 && gx < HH)
                v = inN[(size_t)cin * HH * HH + gy * HH + gx];
            if (SIGN_IN) v = (v > 0.f) ? 1.f : ((v < 0.f) ? -1.f : 0.f);
            Bs[r][c] = v;
        }
        __syncthreads();
#pragma unroll
        for (int tap = 0; tap < 9; tap++) {
            int dy = tap / 3, dx = tap % 3;
            float4 wv = *(const float4*)&As[tap][oc_t * 4];
#pragma unroll
            for (int j = 0; j < 4; j++) {
                int p = pos_t + 16 * j;
                float bv = Bs[(p >> 3) + dy][(p & 7) + dx];
                acc[j][0] += bv * wv.x;
                acc[j][1] += bv * wv.y;
                acc[j][2] += bv * wv.z;
                acc[j][3] += bv * wv.w;
            }
        }
        __syncthreads();
    }

#pragma unroll
    for (int j = 0; j < 4; j++) {
        int p = pos_t + 16 * j;
        int oy = ty0 + (p >> 3), ox = tx0 + (p & 7);
#pragma unroll
        for (int i = 0; i < 4; i++) {
            int oc = oc0 + oc_t * 4 + i;
            out[(((size_t)n * Cout + oc) * HH + oy) * HH + ox] = acc[j][i];
        }
    }
}

// ---------------- bf16 pack/convert helpers ----------------
// pack: lower half = bf16(evenk), upper half = bf16(oddk)
__device__ __forceinline__ uint32_t bf16pack(float evenk, float oddk) {
    uint32_t r;
    asm("cvt.rn.bf16x2.f32 %0, %1, %2;" : "=r"(r) : "f"(oddk), "f"(evenk));
    return r;
}
__device__ __forceinline__ float bf16lo_f(uint32_t p) { return __uint_as_float(p << 16); }
__device__ __forceinline__ float bf16hi_f(uint32_t p) { return __uint_as_float(p & 0xFFFF0000u); }

// m16n8k16 bf16 MMA, f32 accumulate
__device__ __forceinline__ void mma_bf16(float* d, const uint32_t* a, const uint32_t* b) {
    asm volatile(
        "mma.sync.aligned.m16n8k16.row.col.f32.bf16.bf16.f32 "
        "{%0,%1,%2,%3}, {%4,%5,%6,%7}, {%8,%9}, {%0,%1,%2,%3};\n"
        : "+f"(d[0]), "+f"(d[1]), "+f"(d[2]), "+f"(d[3])
        : "r"(a[0]), "r"(a[1]), "r"(a[2]), "r"(a[3]),
          "r"(b[0]), "r"(b[1]));
}

// ---------------- implicit-GEMM conv via bf16 MMA (m16n8k16) ----------------
// Block: M=128 (oc) x N=64 (positions). 128 threads, 4 warps; warp tile 32x64.
// K = CIN*9, chunked by 16 (one k16 MMA step per chunk).
// SPLIT=true: bf16x2 decomposition (hi/lo, 3 MMAs) for ~16-bit mantissa (real branch).
// SPLIT=false: single bf16 plane (binary branch: +-1/0 exact).
template<int CIN, int H, bool SIGN_IN, bool SPLIT>
__global__ void __launch_bounds__(128) convmma_k(const float* __restrict__ in,
                                                 const float* __restrict__ w,
                                                 float* __restrict__ out,
                                                 int Cout) {
    constexpr int Wd = H;
    constexpr int HW = H * H;
    constexpr int K  = CIN * 9;
    constexpr int LGHW = (HW == 1024) ? 10 : (HW == 256) ? 8 : 6;
    constexpr int LGW  = (H == 32) ? 5 : (H == 16) ? 4 : 3;
    constexpr int NS = SPLIT ? 2 : 1;

    __shared__ uint32_t As[NS][8][136];  // [plane][kpair][m] packed bf16x2
    __shared__ uint32_t Bs[NS][8][72];   // [plane][kpair][n]

    int tid  = threadIdx.x;
    int lane = tid & 31;
    int warp = tid >> 5;
    int gid  = lane >> 2;   // 0..7
    int tig  = lane & 3;    // 0..3

    int col0 = blockIdx.x * 64;
    int oc0  = blockIdx.y * 128;

    // B-gather mapping: thread handles column bc, k-rows br2*8 + i (i=0..7)
    int bc  = tid & 63;
    int br2 = tid >> 6;     // 0 or 1
    int gcol = col0 + bc;
    int n   = gcol >> LGHW;
    int pos = gcol & (HW - 1);
    int y   = pos >> LGW;
    int x   = pos & (Wd - 1);
    const float* inN = in + (size_t)n * CIN * HW;

    int cin8[8], tap8[8];
#pragma unroll
    for (int i = 0; i < 8; i++) {
        int r = br2 * 8 + i;
        cin8[i] = r / 9;
        tap8[i] = r % 9;
    }

    float acc[2][8][4];
#pragma unroll
    for (int mt = 0; mt < 2; mt++)
#pragma unroll
        for (int nt = 0; nt < 8; nt++)
#pragma unroll
            for (int r = 0; r < 4; r++) acc[mt][nt][r] = 0.f;

    const float* wA = w + (size_t)(oc0 + tid) * K;

    for (int k0 = 0; k0 < K; k0 += 16) {
        // ---- stage A (weights): thread = one oc row, 16 k values ----
#pragma unroll
        for (int j = 0; j < 4; j++) {
            float4 v = *(const float4*)(wA + k0 + 4 * j);
            uint32_t h0 = bf16pack(v.x, v.y);
            uint32_t h1 = bf16pack(v.z, v.w);
            As[0][2 * j + 0][tid] = h0;
            As[0][2 * j + 1][tid] = h1;
            if (SPLIT) {
                As[1][2 * j + 0][tid] = bf16pack(v.x - bf16lo_f(h0), v.y - bf16hi_f(h0));
                As[1][2 * j + 1][tid] = bf16pack(v.z - bf16lo_f(h1), v.w - bf16hi_f(h1));
            }
        }
        // ---- stage B (im2col gather) ----
        float bv[8];
#pragma unroll
        for (int i = 0; i < 8; i++) {
            int tap = tap8[i];
            int yy = y + tap / 3 - 1;
            int xx = x + tap % 3 - 1;
            float v = 0.f;
            if (yy >= 0 && yy < H && xx >= 0 && xx < Wd)
                v = inN[cin8[i] * HW + yy * Wd + xx];
            if (SIGN_IN) v = (v > 0.f) ? 1.f : ((v < 0.f) ? -1.f : 0.f);
            bv[i] = v;
            // advance k by 16: cin += 1, tap += 7 (carry)
            tap8[i] += 7;
            cin8[i] += 1;
            if (tap8[i] >= 9) { tap8[i] -= 9; cin8[i] += 1; }
        }
#pragma unroll
        for (int t = 0; t < 4; t++) {
            uint32_t h = bf16pack(bv[2 * t], bv[2 * t + 1]);
            Bs[0][br2 * 4 + t][bc] = h;
            if (SPLIT)
                Bs[1][br2 * 4 + t][bc] =
                    bf16pack(bv[2 * t] - bf16lo_f(h), bv[2 * t + 1] - bf16hi_f(h));
        }
        __syncthreads();

        // ---- MMA step (one k16 per chunk) ----
        uint32_t af[NS][2][4], bf[NS][8][2];
#pragma unroll
        for (int s = 0; s < NS; s++) {
#pragma unroll
            for (int mt = 0; mt < 2; mt++) {
                int m0 = warp * 32 + mt * 16 + gid;
                af[s][mt][0] = As[s][tig][m0];
                af[s][mt][1] = As[s][tig][m0 + 8];
                af[s][mt][2] = As[s][tig + 4][m0];
                af[s][mt][3] = As[s][tig + 4][m0 + 8];
            }
#pragma unroll
            for (int nt = 0; nt < 8; nt++) {
                bf[s][nt][0] = Bs[s][tig][nt * 8 + gid];
                bf[s][nt][1] = Bs[s][tig + 4][nt * 8 + gid];
            }
        }
#pragma unroll
        for (int mt = 0; mt < 2; mt++)
#pragma unroll
            for (int nt = 0; nt < 8; nt++) {
                if (SPLIT) {
                    mma_bf16(acc[mt][nt], af[1][mt], bf[0][nt]);  // lo*hi
                    mma_bf16(acc[mt][nt], af[0][mt], bf[1][nt]);  // hi*lo
                }
                mma_bf16(acc[mt][nt], af[0][mt], bf[0][nt]);      // hi*hi
            }
        __syncthreads();
    }

    // epilogue: adjacent column pairs -> float2 stores
#pragma unroll
    for (int mt = 0; mt < 2; mt++) {
#pragma unroll
        for (int nt = 0; nt < 8; nt++) {
            int c = col0 + nt * 8 + 2 * tig;
            int n_  = c >> LGHW;
            int pp  = c & (HW - 1);
#pragma unroll
            for (int h = 0; h < 2; h++) {
                int m = oc0 + warp * 32 + mt * 16 + gid + 8 * h;
                float2 v = make_float2(acc[mt][nt][2 * h], acc[mt][nt][2 * h + 1]);
                *(float2*)&out[((size_t)n_ * Cout + m) * HW + pp] = v;
            }
        }
    }
}

// ---------------- BN stats ----------------
__global__ void bnstats_k(const float* __restrict__ x, int C, int HW,
                          float* __restrict__ mean, float* __restrict__ rstd) {
    int c = blockIdx.x;
    int tid = threadIdx.x;
    double s1 = 0.0, s2 = 0.0;
    for (int n = 0; n < NB; n++) {
        const float* xp = x + ((size_t)n * C + c) * HW;
        for (int p = tid; p < HW; p += 256) {
            float v = xp[p];
            s1 += (double)v;
            s2 += (double)v * (double)v;
        }
    }
    __shared__ double sh1[256], sh2[256];
    sh1[tid] = s1; sh2[tid] = s2; __syncthreads();
    for (int st = 128; st > 0; st >>= 1) {
        if (tid < st) { sh1[tid] += sh1[tid + st]; sh2[tid] += sh2[tid + st]; }
        __syncthreads();
    }
    if (tid == 0) {
        double M = (double)NB * HW;
        double m = sh1[0] / M;
        double var = sh2[0] / M - m * m;
        mean[c] = (float)m;
        rstd[c] = (float)(1.0 / sqrt(var + 1e-5));
    }
}

// ---------------- BN apply + hardtanh ----------------
__global__ void bnht_k(const float* __restrict__ x, float* __restrict__ y,
                       const float* __restrict__ mean, const float* __restrict__ rstd,
                       const float* __restrict__ g, const float* __restrict__ bb,
                       int lgHW, int Cmask) {
    size_t i = (size_t)blockIdx.x * 256 + threadIdx.x;
    int c = (int)((i >> lgHW) & (size_t)Cmask);
    float v = (x[i] - mean[c]) * rstd[c] * g[c] + bb[c];
    y[i] = fminf(1.f, fmaxf(-1.f, v));
}

// ---------------- 2x2 maxpool ----------------
__global__ void pool_k(const float* __restrict__ x, float* __restrict__ y,
                       int C, int Hout) {
    int i = blockIdx.x * 256 + threadIdx.x;
    int ox = i % Hout; int t = i / Hout;
    int oy = t % Hout; t /= Hout;
    int c = t % C; int n = t / C;
    int Hin = Hout * 2;
    const float* p = x + (((size_t)n * C + c) * Hin + oy * 2) * Hin + ox * 2;
    y[i] = fmaxf(fmaxf(p[0], p[1]), fmaxf(p[Hin], p[Hin + 1]));
}

// ---------------- copy ----------------
__global__ void copy_k(const float* __restrict__ src, float* __restrict__ dst) {
    size_t i = (size_t)blockIdx.x * 256 + threadIdx.x;
    dst[i] = src[i];
}

// ---------------- FC ----------------
__global__ void fc_k(const float* __restrict__ p, const float* __restrict__ w,
                     const float* __restrict__ b, float* __restrict__ out) {
    int n = blockIdx.x;
    int tid = threadIdx.x;
    float acc[10];
#pragma unroll
    for (int j = 0; j < 10; j++) acc[j] = 0.f;
    const float* pn = p + (size_t)n * 8192;
    for (int k = tid; k < 8192; k += 256) {
        float pv = pn[k];
#pragma unroll
        for (int j = 0; j < 10; j++) acc[j] += pv * w[(size_t)j * 8192 + k];
    }
    __shared__ float sh[256];
    for (int j = 0; j < 10; j++) {
        sh[tid] = acc[j]; __syncthreads();
        for (int st = 128; st > 0; st >>= 1) {
            if (tid < st) sh[tid] += sh[tid + st];
            __syncthreads();
        }
        if (tid == 0) out[n * 10 + j] = sh[0] + b[j];
        __syncthreads();
    }
}

// ---------------- host launch ----------------
extern "C" void kernel_launch(void* const* d_in, const int* in_sizes, int n_in,
                              void* d_out, int out_size) {
    (void)in_sizes; (void)n_in; (void)out_size;
    const float* x   = (const float*)d_in[0];
    const float* w0  = (const float*)d_in[1];
    const float* w1  = (const float*)d_in[2];
    const float* w2  = (const float*)d_in[3];
    const float* w3  = (const float*)d_in[4];
    const float* w4  = (const float*)d_in[5];
    const float* w5  = (const float*)d_in[6];
    const float* fcw = (const float*)d_in[7];
    const float* fcb = (const float*)d_in[8];
    const float* G[6], *B[6];
    for (int i = 0; i < 6; i++) { G[i] = (const float*)d_in[9 + 2*i]; B[i] = (const float*)d_in[10 + 2*i]; }
    float* out = (float*)d_out;

    float *convB, *convR, *xb, *poolB, *poolR, *bw, *mean, *rstd;
    cudaGetSymbolAddress((void**)&convB, g_convB);
    cudaGetSymbolAddress((void**)&convR, g_convR);
    cudaGetSymbolAddress((void**)&xb,    g_x);
    cudaGetSymbolAddress((void**)&poolB, g_poolB);
    cudaGetSymbolAddress((void**)&poolR, g_poolR);
    cudaGetSymbolAddress((void**)&bw,    g_bw);
    cudaGetSymbolAddress((void**)&mean,  g_mean);
    cudaGetSymbolAddress((void**)&rstd,  g_rstd);

    // launch order arranged so ncu (-s 5 -c 1) profiles the binary convmma L1:
    // 0: conv0, 1: wsign1, 2: bnstats0, 3: bnht0, 4: wsign2, 5: convmma L1b <- profiled
    conv3x3_k<3, 32, false><<<dim3(16, 2, NB), 256>>>(x, w0, convB);
    wsign_k<<<128, 256>>>(w1, bw + BW1, 128 * 9);
    bnstats_k<<<128, 256>>>(convB, 128, 1024, mean, rstd);
    bnht_k<<<(NB * 128 * 1024) / 256, 256>>>(convB, xb, mean, rstd, G[0], B[0], 10, 127);
    wsign_k<<<256, 256>>>(w2, bw + BW2, 128 * 9);

    // Layer 1: 128->128 @32, pool -> 16
    convmma_k<128, 32, true,  false><<<dim3(2048, 1), 128>>>(xb, bw + BW1, convB, 128);
    convmma_k<128, 32, false, true ><<<dim3(2048, 1), 128>>>(xb, w1,       convR, 128);
    wsign_k<<<256, 256>>>(w3, bw + BW3, 256 * 9);
    wsign_k<<<512, 256>>>(w4, bw + BW4, 256 * 9);
    wsign_k<<<512, 256>>>(w5, bw + BW5, 512 * 9);
    pool_k<<<(NB * 128 * 256) / 256, 256>>>(convB, poolB, 128, 16);
    pool_k<<<(NB * 128 * 256) / 256, 256>>>(convR, poolR, 128, 16);
    bnstats_k<<<128, 256>>>(poolB, 128, 256, mean, rstd);
    bnht_k<<<(NB * 128 * 256) / 256, 256>>>(poolB, out + O_L1B, mean, rstd, G[1], B[1], 8, 127);
    bnstats_k<<<128, 256>>>(poolR, 128, 256, mean + 512, rstd + 512);
    bnht_k<<<(NB * 128 * 256) / 256, 256>>>(poolR, out + O_L1R, mean + 512, rstd + 512, G[1], B[1], 8, 127);

    // Layer 2: 128->256 @16
    convmma_k<128, 16, true,  false><<<dim3(512, 2), 128>>>(out + O_L1B, bw + BW2, convB, 256);
    convmma_k<128, 16, false, true ><<<dim3(512, 2), 128>>>(out + O_L1R, w2,       convR, 256);
    bnstats_k<<<256, 256>>>(convB, 256, 256, mean, rstd);
    bnht_k<<<(NB * 256 * 256) / 256, 256>>>(convB, out + O_L2B, mean, rstd, G[2], B[2], 8, 255);
    bnstats_k<<<256, 256>>>(convR, 256, 256, mean + 512, rstd + 512);
    bnht_k<<<(NB * 256 * 256) / 256, 256>>>(convR, out + O_L2R, mean + 512, rstd + 512, G[2], B[2], 8, 255);

    // Layer 3: 256->256 @16, pool -> 8
    convmma_k<256, 16, true,  false><<<dim3(512, 2), 128>>>(out + O_L2B, bw + BW3, convB, 256);
    convmma_k<256, 16, false, true ><<<dim3(512, 2), 128>>>(out + O_L2R, w3,       convR, 256);
    pool_k<<<(NB * 256 * 64) / 256, 256>>>(convB, poolB, 256, 8);
    pool_k<<<(NB * 256 * 64) / 256, 256>>>(convR, poolR, 256, 8);
    bnstats_k<<<256, 256>>>(poolB, 256, 64, mean, rstd);
    bnht_k<<<(NB * 256 * 64) / 256, 256>>>(poolB, out + O_L3B, mean, rstd, G[3], B[3], 6, 255);
    bnstats_k<<<256, 256>>>(poolR, 256, 64, mean + 512, rstd + 512);
    bnht_k<<<(NB * 256 * 64) / 256, 256>>>(poolR, out + O_L3R, mean + 512, rstd + 512, G[3], B[3], 6, 255);

    // Layer 4: 256->512 @8
    convmma_k<256, 8, true,  false><<<dim3(128, 4), 128>>>(out + O_L3B, bw + BW4, convB, 512);
    convmma_k<256, 8, false, true ><<<dim3(128, 4), 128>>>(out + O_L3R, w4,       convR, 512);
    bnstats_k<<<512, 256>>>(convB, 512, 64, mean, rstd);
    bnht_k<<<(NB * 512 * 64) / 256, 256>>>(convB, out + O_L4B, mean, rstd, G[4], B[4], 6, 511);
    bnstats_k<<<512, 256>>>(convR, 512, 64, mean + 512, rstd + 512);
    bnht_k<<<(NB * 512 * 64) / 256, 256>>>(convR, out + O_L4R, mean + 512, rstd + 512, G[4], B[4], 6, 511);

    // Layer 5: 512->512 @8, pool -> 4
    convmma_k<512, 8, true,  false><<<dim3(128, 4), 128>>>(out + O_L4B, bw + BW5, convB, 512);
    convmma_k<512, 8, false, true ><<<dim3(128, 4), 128>>>(out + O_L4R, w5,       convR, 512);
    pool_k<<<(NB * 512 * 16) / 256, 256>>>(convB, poolB, 512, 4);
    pool_k<<<(NB * 512 * 16) / 256, 256>>>(convR, poolR, 512, 4);
    bnstats_k<<<512, 256>>>(poolB, 512, 16, mean, rstd);
    bnht_k<<<(NB * 512 * 16) / 256, 256>>>(poolB, out + O_L5B, mean, rstd, G[5], B[5], 4, 511);
    bnstats_k<<<512, 256>>>(poolR, 512, 16, mean + 512, rstd + 512);
    bnht_k<<<(NB * 512 * 16) / 256, 256>>>(poolR, out + O_L5R, mean + 512, rstd + 512, G[5], B[5], 4, 511);

    // penul + FC
    copy_k<<<(NB * 8192) / 256, 256>>>(out + O_L5B, out + O_PENUL);
    fc_k<<<NB, 256>>>(out + O_PENUL, fcw, fcb, out + O_OUT);
}